// round 7
// baseline (speedup 1.0000x reference)
#include <cuda_runtime.h>
#include <math.h>

#define GAMMA_F 0.99f
#define TAU 64          // tau == tauP == 64
#define BPB 8           // batch elements per group
#define NG 2            // groups per CTA (software pipeline)
#define THREADS 256     // 8 warps
#define NW (THREADS / 32)

// Each CTA: 16 batch elements as 2 pipelined groups of 8.
// All gather LDGs (both groups) issue up front (MLP=8/thread); group 0 is
// computed while group 1's loads are in flight, hiding the L2/DRAM latency.
__global__ void __launch_bounds__(THREADS)
iqn_td_fused_kernel(const float* __restrict__ q,          // (tau, B, N)
                    const float* __restrict__ next_n_q,   // (tauP, B, N)
                    const int*   __restrict__ action,     // (B,)
                    const int*   __restrict__ next_action,// (B,)
                    const float* __restrict__ reward,     // (T, B)
                    const int*   __restrict__ done,       // (B,)
                    const float* __restrict__ replay_q,   // (tau, B)
                    const float* __restrict__ weight,     // (B,)
                    float* __restrict__ out,              // out[0]=loss, out[1..B]=td
                    int B, int N, int T, float gamma_T)
{
    const int tid  = threadIdx.x;
    const int lane = tid & 31;
    const int w    = tid >> 5;               // warp 0..7
    const int b0   = blockIdx.x * (BPB * NG);

    __shared__ float s_qsa[NG][TAU][BPB];
    __shared__ float s_tgt[NG][TAU][BPB];
    __shared__ int   s_a[NG * BPB], s_an[NG * BPB];
    __shared__ float s_rsum[NG * BPB], s_coef[NG * BPB];
    __shared__ float s_red[NG][NW][BPB];

    // ---- prelude: per-b scalars for both groups ----
    if (tid < NG * BPB) {
        const int b = b0 + tid;
        s_a[tid]  = action[b];
        s_an[tid] = next_action[b];
        float r_sum = 0.0f, g = 1.0f;
        for (int tt = 0; tt < T; ++tt) {
            r_sum = fmaf(g, reward[tt * B + b], r_sum);
            g *= GAMMA_F;
        }
        s_rsum[tid] = r_sum;
        s_coef[tid] = (done[b] != 0) ? 0.0f : gamma_T;
    }
    __syncthreads();

    // ---- gather: issue ALL 8 LDGs (2 groups x 2 taus x 2 arrays) ----
    const int gbl = lane & 7;                // b_local within group
    const int ts  = lane >> 3;               // 0..3
    float g1_q[2], g1_n[2];                  // group-1 values held in regs
    float rs1, cf1;
    {
        const int   a0  = s_a[gbl],        an0 = s_an[gbl];
        const int   a1  = s_a[BPB + gbl],  an1 = s_an[BPB + gbl];
        const float rs0 = s_rsum[gbl],     cf0 = s_coef[gbl];
        rs1 = s_rsum[BPB + gbl];
        cf1 = s_coef[BPB + gbl];
        const size_t plane = (size_t)B * (size_t)N;
        const size_t row0  = (size_t)(b0 + gbl) * (size_t)N;
        const size_t row1  = (size_t)(b0 + BPB + gbl) * (size_t)N;

        float g0_q[2], g0_n[2];
        #pragma unroll
        for (int k = 0; k < 2; ++k) {        // taus: k*32 + w*4 + ts
            const int t = k * 32 + w * 4 + ts;
            const size_t base0 = (size_t)t * plane + row0;
            const size_t base1 = (size_t)t * plane + row1;
            g0_q[k] = q[base0 + a0];
            g0_n[k] = next_n_q[base0 + an0];
            g1_q[k] = q[base1 + a1];         // in-flight through G0 compute
            g1_n[k] = next_n_q[base1 + an1];
        }
        #pragma unroll
        for (int k = 0; k < 2; ++k) {
            const int t = k * 32 + w * 4 + ts;
            s_qsa[0][t][gbl] = g0_q[k];
            s_tgt[0][t][gbl] = fmaf(cf0, g0_n[k], rs0);
        }
    }
    __syncthreads();                          // group 0 ready

    // ---- compute mapping: thread = (b = tid&7, taus = (tid>>3)*2, +1) ----
    const int cbl = tid & 7;
    const int tb  = (tid >> 3) * 2;

    // rq for both groups (coalesced, L2-hot)
    float rq[NG][2], rq1[NG][2];
    #pragma unroll
    for (int j = 0; j < 2; ++j) {
        rq[0][j]  = replay_q[(tb + j) * B + b0 + cbl];
        rq[1][j]  = replay_q[(tb + j) * B + b0 + BPB + cbl];
        rq1[0][j] = 1.0f - rq[0][j];
        rq1[1][j] = 1.0f - rq[1][j];
    }

    // ---- compute group 0 ----
    {
        float qsa0 = s_qsa[0][tb][cbl], qsa1 = s_qsa[0][tb + 1][cbl];
        float a0 = 0.0f, a1 = 0.0f;
        #pragma unroll 16
        for (int tp = 0; tp < TAU; ++tp) {
            const float tgt = s_tgt[0][tp][cbl];
            {
                const float u = tgt - qsa0, au = fabsf(u);
                const float c = fminf(au, 1.0f);
                const float h = fmaf(c, fmaf(0.5f, c, -1.0f), au);
                a0 = fmaf((u < 0.0f) ? rq1[0][0] : rq[0][0], h, a0);
            }
            {
                const float u = tgt - qsa1, au = fabsf(u);
                const float c = fminf(au, 1.0f);
                const float h = fmaf(c, fmaf(0.5f, c, -1.0f), au);
                a1 = fmaf((u < 0.0f) ? rq1[0][1] : rq[0][1], h, a1);
            }
        }
        float part = a0 + a1;
        part += __shfl_down_sync(0xffffffffu, part, 16);
        part += __shfl_down_sync(0xffffffffu, part, 8);
        if (lane < 8) s_red[0][w][lane] = part;
    }

    // ---- stage group 1 into smem (loads have had ~full compute to land) ----
    #pragma unroll
    for (int k = 0; k < 2; ++k) {
        const int t = k * 32 + w * 4 + ts;
        s_qsa[1][t][gbl] = g1_q[k];
        s_tgt[1][t][gbl] = fmaf(cf1, g1_n[k], rs1);
    }
    __syncthreads();                          // group 1 ready (+ s_red[0] visible)

    // ---- compute group 1 ----
    {
        float qsa0 = s_qsa[1][tb][cbl], qsa1 = s_qsa[1][tb + 1][cbl];
        float a0 = 0.0f, a1 = 0.0f;
        #pragma unroll 16
        for (int tp = 0; tp < TAU; ++tp) {
            const float tgt = s_tgt[1][tp][cbl];
            {
                const float u = tgt - qsa0, au = fabsf(u);
                const float c = fminf(au, 1.0f);
                const float h = fmaf(c, fmaf(0.5f, c, -1.0f), au);
                a0 = fmaf((u < 0.0f) ? rq1[1][0] : rq[1][0], h, a0);
            }
            {
                const float u = tgt - qsa1, au = fabsf(u);
                const float c = fminf(au, 1.0f);
                const float h = fmaf(c, fmaf(0.5f, c, -1.0f), au);
                a1 = fmaf((u < 0.0f) ? rq1[1][1] : rq[1][1], h, a1);
            }
        }
        float part = a0 + a1;
        part += __shfl_down_sync(0xffffffffu, part, 16);
        part += __shfl_down_sync(0xffffffffu, part, 8);
        if (lane < 8) s_red[1][w][lane] = part;
    }
    __syncthreads();

    // ---- epilogue: 16 lanes finalize 16 b's, one atomic per CTA ----
    if (tid < NG * BPB) {
        const int b = b0 + tid;                      // tid<8 -> g0, 8..15 -> g1
        const int g = tid >> 3, bl = tid & 7;
        float tot = 0.0f;
        #pragma unroll
        for (int k = 0; k < NW; ++k)
            tot += s_red[g][k][bl];
        const float td = tot * (1.0f / (float)TAU);  // mean over tauP
        out[1 + b] = td;
        float wsum = td * weight[b];
        wsum += __shfl_down_sync(0x0000ffffu, wsum, 8);
        wsum += __shfl_down_sync(0x0000ffffu, wsum, 4);
        wsum += __shfl_down_sync(0x0000ffffu, wsum, 2);
        wsum += __shfl_down_sync(0x0000ffffu, wsum, 1);
        if (tid == 0)
            atomicAdd(out, wsum * (1.0f / (float)B));
    }
}

extern "C" void kernel_launch(void* const* d_in, const int* in_sizes, int n_in,
                              void* d_out, int out_size)
{
    const float* q        = (const float*)d_in[0];
    const float* next_n_q = (const float*)d_in[1];
    const int*   action   = (const int*)  d_in[2];
    const int*   naction  = (const int*)  d_in[3];
    const float* reward   = (const float*)d_in[4];
    const int*   done     = (const int*)  d_in[5];
    const float* replay_q = (const float*)d_in[6];
    const float* weight   = (const float*)d_in[7];

    const int B   = in_sizes[2];
    const int tau = in_sizes[6] / B;
    const int N   = in_sizes[0] / (tau * B);
    const int T   = in_sizes[4] / B;

    float gamma_T = 1.0f;
    for (int i = 0; i < T; ++i) gamma_T *= GAMMA_F;

    float* out = (float*)d_out;

    cudaMemsetAsync(out, 0, sizeof(float), 0);   // zero loss accumulator

    iqn_td_fused_kernel<<<B / (BPB * NG), THREADS>>>(q, next_n_q, action, naction,
                                                     reward, done, replay_q, weight,
                                                     out, B, N, T, gamma_T);
}

// round 8
// speedup vs baseline: 1.0354x; 1.0354x over previous
#include <cuda_runtime.h>
#include <math.h>

#define GAMMA_F 0.99f
#define TAU 64          // tau == tauP == 64
#define BPB 8           // batch elements per block
#define THREADS 256     // 8 warps
#define NW (THREADS / 32)
#define TROW (TAU + 4)  // padded row (floats) for s_tgt: 272B, breaks bank aliasing

// R6 skeleton (grid=512, 256 thr: best measured) with:
//  - prelude sync removed (per-thread scalar loads)
//  - targets transposed [b][tp] + padded -> LDS.128 reads in the pair loop
//  - 4 accumulator chains
__global__ void __launch_bounds__(THREADS)
iqn_td_fused_kernel(const float* __restrict__ q,          // (tau, B, N)
                    const float* __restrict__ next_n_q,   // (tauP, B, N)
                    const int*   __restrict__ action,     // (B,)
                    const int*   __restrict__ next_action,// (B,)
                    const float* __restrict__ reward,     // (T, B)
                    const int*   __restrict__ done,       // (B,)
                    const float* __restrict__ replay_q,   // (tau, B)
                    const float* __restrict__ weight,     // (B,)
                    float* __restrict__ out,              // out[0]=loss, out[1..B]=td
                    int B, int N, int T, float gamma_T)
{
    const int tid  = threadIdx.x;
    const int lane = tid & 31;
    const int w    = tid >> 5;               // warp 0..7
    const int b0   = blockIdx.x * BPB;

    __shared__ float s_qsa[TAU][BPB];                    // [t][b]
    __shared__ __align__(16) float s_tgt[BPB][TROW];     // [b][tp], padded
    __shared__ float s_red[NW][BPB];

    // ---- gather setup: every thread loads its own per-b scalars ----
    const int bl = lane & 7;                 // b_local
    const int ts = lane >> 3;                // 0..3
    const int bg = b0 + bl;

    const int   a    = action[bg];
    const int   an   = next_action[bg];
    float r_sum = 0.0f, g = 1.0f;
    #pragma unroll 4
    for (int tt = 0; tt < T; ++tt) {
        r_sum = fmaf(g, reward[tt * B + bg], r_sum);
        g *= GAMMA_F;
    }
    const float coef = (done[bg] != 0) ? 0.0f : gamma_T;

    // ---- gather: warp covers 4 taus x 8 b per pass, 2 passes ----
    {
        const size_t plane = (size_t)B * (size_t)N;
        const size_t rowb  = (size_t)bg * (size_t)N;
        float gq[2], gn[2];
        #pragma unroll
        for (int k = 0; k < 2; ++k) {        // taus: k*32 + w*4 + ts
            const int t = k * 32 + w * 4 + ts;
            const size_t base = (size_t)t * plane + rowb;
            gq[k] = q[base + a];
            gn[k] = next_n_q[base + an];
        }
        #pragma unroll
        for (int k = 0; k < 2; ++k) {
            const int t = k * 32 + w * 4 + ts;
            s_qsa[t][bl]  = gq[k];                       // conflict-free STS
            s_tgt[bl][t]  = fmaf(coef, gn[k], r_sum);    // conflict-free STS
        }
    }

    // rq loads (coalesced, independent of smem) before the sync
    const int cbl = tid & 7;
    const int tb  = (tid >> 3) * 2;
    const float rqa  = replay_q[tb * B + b0 + cbl];
    const float rqb  = replay_q[(tb + 1) * B + b0 + cbl];
    const float rqa1 = 1.0f - rqa;
    const float rqb1 = 1.0f - rqb;

    __syncthreads();

    // ---- compute: thread = (b = cbl, taus tb, tb+1); LDS.128 over tps ----
    const float qsa0 = s_qsa[tb][cbl];
    const float qsa1 = s_qsa[tb + 1][cbl];
    const float4* __restrict__ trow = (const float4*)&s_tgt[cbl][0];

    float acc0e = 0.0f, acc0o = 0.0f, acc1e = 0.0f, acc1o = 0.0f;
    #pragma unroll
    for (int j4 = 0; j4 < TAU / 4; ++j4) {
        const float4 t4 = trow[j4];          // 4 targets, one LDS.128
        // kappa=1: c=min(|u|,1); h=c*(0.5c-1)+|u|; f=(u<0)?(1-rq):rq
        {   const float u = t4.x - qsa0, au = fabsf(u), c = fminf(au, 1.0f);
            acc0e = fmaf((u < 0.0f) ? rqa1 : rqa, fmaf(c, fmaf(0.5f, c, -1.0f), au), acc0e); }
        {   const float u = t4.x - qsa1, au = fabsf(u), c = fminf(au, 1.0f);
            acc1e = fmaf((u < 0.0f) ? rqb1 : rqb, fmaf(c, fmaf(0.5f, c, -1.0f), au), acc1e); }
        {   const float u = t4.y - qsa0, au = fabsf(u), c = fminf(au, 1.0f);
            acc0o = fmaf((u < 0.0f) ? rqa1 : rqa, fmaf(c, fmaf(0.5f, c, -1.0f), au), acc0o); }
        {   const float u = t4.y - qsa1, au = fabsf(u), c = fminf(au, 1.0f);
            acc1o = fmaf((u < 0.0f) ? rqb1 : rqb, fmaf(c, fmaf(0.5f, c, -1.0f), au), acc1o); }
        {   const float u = t4.z - qsa0, au = fabsf(u), c = fminf(au, 1.0f);
            acc0e = fmaf((u < 0.0f) ? rqa1 : rqa, fmaf(c, fmaf(0.5f, c, -1.0f), au), acc0e); }
        {   const float u = t4.z - qsa1, au = fabsf(u), c = fminf(au, 1.0f);
            acc1e = fmaf((u < 0.0f) ? rqb1 : rqb, fmaf(c, fmaf(0.5f, c, -1.0f), au), acc1e); }
        {   const float u = t4.w - qsa0, au = fabsf(u), c = fminf(au, 1.0f);
            acc0o = fmaf((u < 0.0f) ? rqa1 : rqa, fmaf(c, fmaf(0.5f, c, -1.0f), au), acc0o); }
        {   const float u = t4.w - qsa1, au = fabsf(u), c = fminf(au, 1.0f);
            acc1o = fmaf((u < 0.0f) ? rqb1 : rqb, fmaf(c, fmaf(0.5f, c, -1.0f), au), acc1o); }
    }

    // ---- reduce within warp over the 4 tau-groups sharing each bl ----
    float part = (acc0e + acc0o) + (acc1e + acc1o);
    part += __shfl_down_sync(0xffffffffu, part, 16);
    part += __shfl_down_sync(0xffffffffu, part, 8);
    if (lane < 8) s_red[w][lane] = part;
    __syncthreads();

    // ---- epilogue: 8 lanes finalize 8 b's, one atomic per CTA ----
    if (tid < BPB) {
        const int b = b0 + tid;
        float tot = 0.0f;
        #pragma unroll
        for (int k = 0; k < NW; ++k)
            tot += s_red[k][tid];
        const float td = tot * (1.0f / (float)TAU);   // mean over tauP
        out[1 + b] = td;
        float wsum = td * weight[b];
        wsum += __shfl_down_sync(0x000000ffu, wsum, 4);
        wsum += __shfl_down_sync(0x000000ffu, wsum, 2);
        wsum += __shfl_down_sync(0x000000ffu, wsum, 1);
        if (tid == 0)
            atomicAdd(out, wsum * (1.0f / (float)B));
    }
}

extern "C" void kernel_launch(void* const* d_in, const int* in_sizes, int n_in,
                              void* d_out, int out_size)
{
    const float* q        = (const float*)d_in[0];
    const float* next_n_q = (const float*)d_in[1];
    const int*   action   = (const int*)  d_in[2];
    const int*   naction  = (const int*)  d_in[3];
    const float* reward   = (const float*)d_in[4];
    const int*   done     = (const int*)  d_in[5];
    const float* replay_q = (const float*)d_in[6];
    const float* weight   = (const float*)d_in[7];

    const int B   = in_sizes[2];
    const int tau = in_sizes[6] / B;
    const int N   = in_sizes[0] / (tau * B);
    const int T   = in_sizes[4] / B;

    float gamma_T = 1.0f;
    for (int i = 0; i < T; ++i) gamma_T *= GAMMA_F;

    float* out = (float*)d_out;

    cudaMemsetAsync(out, 0, sizeof(float), 0);   // zero loss accumulator

    iqn_td_fused_kernel<<<B / BPB, THREADS>>>(q, next_n_q, action, naction,
                                              reward, done, replay_q, weight,
                                              out, B, N, T, gamma_T);
}